// round 15
// baseline (speedup 1.0000x reference)
#include <cuda_runtime.h>

#define SEQ 262144
#define HID 256
#define L 4                    // timesteps per thread
#define P (SEQ / L)            // 65536 threads
#define TPB 512
#define NWARP (TPB / 32)       // 16
#define GRID (P / TPB)         // 128 CTAs, 1/SM, uniform -> barrier safe
#define NCYCLE 2
#define TS_CTA (TPB * L)       // 2048 timesteps per CTA

typedef unsigned long long ull;

// CTA-total affines, rows as float4 {Ji0,Ji1,Ji2,di}; double buffered
struct AffG { float4 r0, r1, r2; };
__device__ AffG g_tot[2][GRID];

// grid barrier: counters reset by last arriver; flags monotone across replays
__device__ unsigned g_cnt[NCYCLE];
__device__ volatile unsigned g_flag[NCYCLE];

__device__ __forceinline__ float tanh_approx(float x) {
    float y; asm("tanh.approx.f32 %0, %1;" : "=f"(y) : "f"(x)); return y;
}

struct Aff { float J[9]; float d[3]; };

__device__ __forceinline__ Aff aff_identity() {
    Aff a;
    a.J[0] = 1.f; a.J[1] = 0.f; a.J[2] = 0.f;
    a.J[3] = 0.f; a.J[4] = 1.f; a.J[5] = 0.f;
    a.J[6] = 0.f; a.J[7] = 0.f; a.J[8] = 1.f;
    a.d[0] = a.d[1] = a.d[2] = 0.f;
    return a;
}

// result = hi ∘ lo (lo applied first)
__device__ __forceinline__ Aff aff_compose(const Aff& hi, const Aff& lo) {
    Aff r;
#pragma unroll
    for (int i = 0; i < 3; i++) {
#pragma unroll
        for (int j = 0; j < 3; j++) {
            r.J[i * 3 + j] = fmaf(hi.J[i * 3 + 0], lo.J[0 * 3 + j],
                             fmaf(hi.J[i * 3 + 1], lo.J[1 * 3 + j],
                                  hi.J[i * 3 + 2] * lo.J[2 * 3 + j]));
        }
        r.d[i] = fmaf(hi.J[i * 3 + 0], lo.d[0],
                 fmaf(hi.J[i * 3 + 1], lo.d[1],
                 fmaf(hi.J[i * 3 + 2], lo.d[2], hi.d[i])));
    }
    return r;
}

__device__ __forceinline__ Aff aff_shfl_up(const Aff& a, int off) {
    Aff r;
#pragma unroll
    for (int i = 0; i < 9; i++) r.J[i] = __shfl_up_sync(0xFFFFFFFFu, a.J[i], off);
#pragma unroll
    for (int i = 0; i < 3; i++) r.d[i] = __shfl_up_sync(0xFFFFFFFFu, a.d[i], off);
    return r;
}

#define FMA2(d, a, bb, c) \
    asm("fma.rn.f32x2 %0, %1, %2, %3;" : "=l"(d) : "l"(a), "l"(bb), "l"(c))

__device__ __forceinline__ ull pk2(float a, float b) {
    ull r; asm("mov.b64 %0, {%1, %2};" : "=l"(r) : "f"(a), "f"(b)); return r;
}
__device__ __forceinline__ void unpk2(float& lo, float& hi, ull d) {
    asm("mov.b64 {%0, %1}, %2;" : "=f"(lo), "=f"(hi) : "l"(d));
}

// ---------------------------------------------------------------------------
// One correction cycle: warp KS scan, CTA combine, publish, grid barrier,
// cross-CTA scan, Newton update of s.
// ---------------------------------------------------------------------------
__device__ __forceinline__ void correction_cycle(
    const Aff& m, int cycle, int tid, int lane, int wid, int cta,
    Aff* warpTot, Aff* warpPre, float4* sVall,
    float& s0, float& s1, float& s2)
{
    int buf = cycle & 1;

    // warp inclusive Kogge-Stone + thread-exclusive
    Aff inc = m;
#pragma unroll
    for (int off = 1; off < 32; off <<= 1) {
        Aff o = aff_shfl_up(inc, off);
        if (lane >= off) inc = aff_compose(inc, o);
    }
    Aff exc = aff_shfl_up(inc, 1);
    if (lane == 0) exc = aff_identity();
    if (lane == 31) warpTot[wid] = inc;
    __syncthreads();

    // thread 0: CTA combine over 16 warp totals, publish, barrier
    if (tid == 0) {
        Aff run = aff_identity();
#pragma unroll
        for (int w = 0; w < NWARP; w++) {
            warpPre[w] = run;
            run = aff_compose(warpTot[w], run);
        }
        AffG t;
        t.r0 = make_float4(run.J[0], run.J[1], run.J[2], run.d[0]);
        t.r1 = make_float4(run.J[3], run.J[4], run.J[5], run.d[1]);
        t.r2 = make_float4(run.J[6], run.J[7], run.J[8], run.d[2]);
        g_tot[buf][cta] = t;
        __threadfence();
        unsigned old = g_flag[cycle];
        unsigned n = atomicAdd(&g_cnt[cycle], 1u);
        if (n == GRID - 1) {
            g_cnt[cycle] = 0;          // clean for next graph replay
            __threadfence();
            g_flag[cycle] = old + 1u;  // release immediately
        } else {
            while (g_flag[cycle] == old) {}
        }
        __threadfence();
    }
    __syncthreads();

    // warp 0: parallel scan over all 128 CTA totals -> V vectors
    if (wid == 0) {
        Aff t4[4];
#pragma unroll
        for (int r = 0; r < 4; r++) {
            int c = 4 * lane + r;
            float4 q0 = __ldcg(&g_tot[buf][c].r0);
            float4 q1 = __ldcg(&g_tot[buf][c].r1);
            float4 q2 = __ldcg(&g_tot[buf][c].r2);
            t4[r].J[0] = q0.x; t4[r].J[1] = q0.y; t4[r].J[2] = q0.z; t4[r].d[0] = q0.w;
            t4[r].J[3] = q1.x; t4[r].J[4] = q1.y; t4[r].J[5] = q1.z; t4[r].d[1] = q1.w;
            t4[r].J[6] = q2.x; t4[r].J[7] = q2.y; t4[r].J[8] = q2.z; t4[r].d[2] = q2.w;
        }
        Aff Pp1 = t4[0];
        Aff Pp2 = aff_compose(t4[1], Pp1);
        Aff Pp3 = aff_compose(t4[2], Pp2);
        Aff laneTot = aff_compose(t4[3], Pp3);
        Aff incL = laneTot;
#pragma unroll
        for (int off = 1; off < 32; off <<= 1) {
            Aff o = aff_shfl_up(incL, off);
            if (lane >= off) incL = aff_compose(incL, o);
        }
        Aff excL = aff_shfl_up(incL, 1);
        if (lane == 0) excL = aff_identity();
        float e0 = excL.d[0], e1 = excL.d[1], e2 = excL.d[2];
        sVall[4 * lane + 0] = make_float4(e0, e1, e2, 0.f);
#define APPLY_STORE(PP, idx)                                                    \
        sVall[4 * lane + idx] = make_float4(                                    \
            fmaf((PP).J[0], e0, fmaf((PP).J[1], e1, fmaf((PP).J[2], e2, (PP).d[0]))), \
            fmaf((PP).J[3], e0, fmaf((PP).J[4], e1, fmaf((PP).J[5], e2, (PP).d[1]))), \
            fmaf((PP).J[6], e0, fmaf((PP).J[7], e1, fmaf((PP).J[8], e2, (PP).d[2]))), 0.f)
        APPLY_STORE(Pp1, 1);
        APPLY_STORE(Pp2, 2);
        APPLY_STORE(Pp3, 3);
#undef APPLY_STORE
    }
    __syncthreads();

    // update: s = exc( warpPre[wid]( V ) )
    float4 V4 = sVall[cta];
    {
        const Aff& p = warpPre[wid];
        float t0 = fmaf(p.J[0], V4.x, fmaf(p.J[1], V4.y, fmaf(p.J[2], V4.z, p.d[0])));
        float t1 = fmaf(p.J[3], V4.x, fmaf(p.J[4], V4.y, fmaf(p.J[5], V4.z, p.d[1])));
        float t2 = fmaf(p.J[6], V4.x, fmaf(p.J[7], V4.y, fmaf(p.J[8], V4.z, p.d[2])));
        s0 = fmaf(exc.J[0], t0, fmaf(exc.J[1], t1, fmaf(exc.J[2], t2, exc.d[0])));
        s1 = fmaf(exc.J[3], t0, fmaf(exc.J[4], t1, fmaf(exc.J[5], t2, exc.d[1])));
        s2 = fmaf(exc.J[6], t0, fmaf(exc.J[7], t1, fmaf(exc.J[8], t2, exc.d[2])));
    }
    __syncthreads();   // protect warpTot/warpPre/sVall reuse
}

// ---------------------------------------------------------------------------
// ONE kernel, TPB=512, L=4:
//  prep (w in regs); cold fine + corr; fine(keep traj) + corr; patch;
//  store membranes; stage trajectory pairs in smem; MLP by threads 0-255
//  (8 ts/thread, 4-pair depth = proven-best shape).
// ---------------------------------------------------------------------------
__global__ void __launch_bounds__(TPB, 1)
fused_kernel(const float* __restrict__ u,
             const float* __restrict__ dtp,
             const float* __restrict__ Ain,
             const float* __restrict__ Bin,
             const float* __restrict__ bAin,
             const float* __restrict__ W1,
             const float* __restrict__ b1,
             const float* __restrict__ W2,
             const float* __restrict__ b2,
             float* __restrict__ out) {
    float* memb = out + 3 * SEQ;

    int tid  = threadIdx.x;
    int lane = tid & 31;
    int wid  = tid >> 5;
    int cta  = blockIdx.x;
    int b    = cta * TPB + tid;

    __shared__ Aff    warpTot[NWARP];
    __shared__ Aff    warpPre[NWARP];
    __shared__ float4 sVall[GRID];        // 2KB
    __shared__ ull    sA[HID * 4];        // 8KB  {w0w0,w1w1,w2w2,b1b1}
    __shared__ ull    sB[HID * 4];        // 8KB  {v0v0,v1v1,v2v2,0}
    __shared__ ull    sX0[TS_CTA / 2];    // 8KB  trajectory pairs ch0
    __shared__ ull    sX1[TS_CTA / 2];    // 8KB  ch1
    __shared__ ull    sX2[TS_CTA / 2];    // 8KB  ch2

    // ---- MLP weight staging (split across threads) ----
    if (tid < HID) {
        int h = tid;
        sA[4 * h + 0] = pk2(W1[3 * h + 0], W1[3 * h + 0]);
        sA[4 * h + 1] = pk2(W1[3 * h + 1], W1[3 * h + 1]);
        sA[4 * h + 2] = pk2(W1[3 * h + 2], W1[3 * h + 2]);
        sA[4 * h + 3] = pk2(b1[h], b1[h]);
    } else if (tid < 2 * HID) {
        int h = tid - HID;
        sB[4 * h + 0] = pk2(W2[h], W2[h]);
        sB[4 * h + 1] = pk2(W2[HID + h], W2[HID + h]);
        sB[4 * h + 2] = pk2(W2[2 * HID + h], W2[2 * HID + h]);
        sB[4 * h + 3] = 0ull;
    }

    float dt = *dtp;
    float A00 = __ldg(Ain + 0), A01 = __ldg(Ain + 1), A02 = __ldg(Ain + 2);
    float A10 = __ldg(Ain + 3), A11 = __ldg(Ain + 4), A12 = __ldg(Ain + 5);
    float A20 = __ldg(Ain + 6), A21 = __ldg(Ain + 7), A22 = __ldg(Ain + 8);

    // ---- prep: w for own 4 timesteps, in registers ----
    float w0r[L], w1r[L], w2r[L];
    {
        float b00 = __ldg(Bin + 0), b01 = __ldg(Bin + 1), b02 = __ldg(Bin + 2);
        float b10 = __ldg(Bin + 3), b11 = __ldg(Bin + 4), b12 = __ldg(Bin + 5);
        float b20 = __ldg(Bin + 6), b21 = __ldg(Bin + 7), b22 = __ldg(Bin + 8);
        float a0 = __ldg(bAin + 0), a1 = __ldg(bAin + 1), a2 = __ldg(bAin + 2);
        const float* ub = u + b * L;
        float4 ua = *(const float4*)(ub);
        float4 va = *(const float4*)(ub + SEQ);
        float4 za = *(const float4*)(ub + 2 * SEQ);
        float U0[4] = {ua.x, ua.y, ua.z, ua.w};
        float U1[4] = {va.x, va.y, va.z, va.w};
        float U2[4] = {za.x, za.y, za.z, za.w};
#pragma unroll
        for (int j = 0; j < L; j++) {
            w0r[j] = fmaf(b00, U0[j], fmaf(b01, U1[j], fmaf(b02, U2[j], a0)));
            w1r[j] = fmaf(b10, U0[j], fmaf(b11, U1[j], fmaf(b12, U2[j], a1)));
            w2r[j] = fmaf(b20, U0[j], fmaf(b21, U1[j], fmaf(b22, U2[j], a2)));
        }
    }

    float s0 = 0.f, s1 = 0.f, s2 = 0.f;
    float xs0[L], xs1[L], xs2[L];

    // ---- two passes: cold fine + corr, then fine(keep traj) + corr ----
#pragma unroll
    for (int cycle = 0; cycle < NCYCLE; cycle++) {
        float x0 = s0, x1 = s1, x2 = s2;
        float SD0 = 0.f, SD1 = 0.f, SD2 = 0.f;
#pragma unroll
        for (int j = 0; j < L; j++) {
            float y0 = fmaf(A00, x0, fmaf(A01, x1, fmaf(A02, x2, w0r[j])));
            float y1 = fmaf(A10, x0, fmaf(A11, x1, fmaf(A12, x2, w1r[j])));
            float y2 = fmaf(A20, x0, fmaf(A21, x1, fmaf(A22, x2, w2r[j])));
            float t0 = tanh_approx(y0);
            float t1 = tanh_approx(y1);
            float t2 = tanh_approx(y2);
            x0 = fmaf(dt, t0, x0);
            x1 = fmaf(dt, t1, x1);
            x2 = fmaf(dt, t2, x2);
            xs0[j] = x0; xs1[j] = x1; xs2[j] = x2;
            SD0 += fmaf(-t0, t0, 1.0f);
            SD1 += fmaf(-t1, t1, 1.0f);
            SD2 += fmaf(-t2, t2, 1.0f);
        }
        Aff m;
        float e0 = dt * SD0, e1 = dt * SD1, e2 = dt * SD2;
        m.J[0] = fmaf(e0, A00, 1.f); m.J[1] = e0 * A01;           m.J[2] = e0 * A02;
        m.J[3] = e1 * A10;           m.J[4] = fmaf(e1, A11, 1.f); m.J[5] = e1 * A12;
        m.J[6] = e2 * A20;           m.J[7] = e2 * A21;           m.J[8] = fmaf(e2, A22, 1.f);
        m.d[0] = x0 - fmaf(m.J[0], s0, fmaf(m.J[1], s1, m.J[2] * s2));
        m.d[1] = x1 - fmaf(m.J[3], s0, fmaf(m.J[4], s1, m.J[5] * s2));
        m.d[2] = x2 - fmaf(m.J[6], s0, fmaf(m.J[7], s1, m.J[8] * s2));

        float sp0 = s0, sp1 = s1, sp2 = s2;
        correction_cycle(m, cycle, tid, lane, wid, cta, warpTot, warpPre, sVall,
                         s0, s1, s2);

        if (cycle == NCYCLE - 1) {
            // patch trajectory by Δs (J ~ I; err ~ |Δ|·L·dt·||A|| ≈ 1e-3·|Δ|)
            float dS0 = s0 - sp0, dS1 = s1 - sp1, dS2 = s2 - sp2;
#pragma unroll
            for (int j = 0; j < L; j++) {
                xs0[j] += dS0; xs1[j] += dS1; xs2[j] += dS2;
            }
        }
    }

    // ---- store membranes + stage pairs in smem ----
    {
        *(float4*)(memb + b * L)           = make_float4(xs0[0], xs0[1], xs0[2], xs0[3]);
        *(float4*)(memb + SEQ + b * L)     = make_float4(xs1[0], xs1[1], xs1[2], xs1[3]);
        *(float4*)(memb + 2 * SEQ + b * L) = make_float4(xs2[0], xs2[1], xs2[2], xs2[3]);
        sX0[2 * tid + 0] = pk2(xs0[0], xs0[1]);
        sX0[2 * tid + 1] = pk2(xs0[2], xs0[3]);
        sX1[2 * tid + 0] = pk2(xs1[0], xs1[1]);
        sX1[2 * tid + 1] = pk2(xs1[2], xs1[3]);
        sX2[2 * tid + 0] = pk2(xs2[0], xs2[1]);
        sX2[2 * tid + 1] = pk2(xs2[2], xs2[3]);
    }
    __syncthreads();

    // ---- MLP: threads 0-255, 8 ts/thread (4 pairs), proven-best shape ----
    if (tid < 256) {
        ull X0[4], X1[4], X2[4], Ac0[4], Ac1[4], Ac2[4];
        ull bz0 = pk2(b2[0], b2[0]), bz1 = pk2(b2[1], b2[1]), bz2 = pk2(b2[2], b2[2]);
#pragma unroll
        for (int k = 0; k < 4; k++) {
            X0[k] = sX0[4 * tid + k];
            X1[k] = sX1[4 * tid + k];
            X2[k] = sX2[4 * tid + k];
            Ac0[k] = bz0; Ac1[k] = bz1; Ac2[k] = bz2;
        }

#pragma unroll 8
        for (int h = 0; h < HID; h++) {
            ulonglong2 a0 = ((const ulonglong2*)sA)[2 * h];       // {w0w0, w1w1}
            ulonglong2 a1 = ((const ulonglong2*)sA)[2 * h + 1];   // {w2w2, bbbb}
            ulonglong2 v0 = ((const ulonglong2*)sB)[2 * h];       // {v0v0, v1v1}
            ulonglong2 v1 = ((const ulonglong2*)sB)[2 * h + 1];   // {v2v2, --}
#pragma unroll
            for (int p = 0; p < 4; p++) {
                ull hv;
                FMA2(hv, a0.x, X0[p], a1.y);
                FMA2(hv, a0.y, X1[p], hv);
                FMA2(hv, a1.x, X2[p], hv);
                float lo, hi;
                unpk2(lo, hi, hv);
                lo = fmaxf(lo, 0.0f);
                hi = fmaxf(hi, 0.0f);
                hv = pk2(lo, hi);
                FMA2(Ac0[p], v0.x, hv, Ac0[p]);
                FMA2(Ac1[p], v0.y, hv, Ac1[p]);
                FMA2(Ac2[p], v1.x, hv, Ac2[p]);
            }
        }

        int tb = cta * TS_CTA + tid * 8;
        float4* q0 = (float4*)(out + tb);
        float4* q1 = (float4*)(out + SEQ + tb);
        float4* q2 = (float4*)(out + 2 * SEQ + tb);
        float l0, h0, l1, h1;
        unpk2(l0, h0, Ac0[0]); unpk2(l1, h1, Ac0[1]);
        q0[0] = make_float4(l0, h0, l1, h1);
        unpk2(l0, h0, Ac0[2]); unpk2(l1, h1, Ac0[3]);
        q0[1] = make_float4(l0, h0, l1, h1);
        unpk2(l0, h0, Ac1[0]); unpk2(l1, h1, Ac1[1]);
        q1[0] = make_float4(l0, h0, l1, h1);
        unpk2(l0, h0, Ac1[2]); unpk2(l1, h1, Ac1[3]);
        q1[1] = make_float4(l0, h0, l1, h1);
        unpk2(l0, h0, Ac2[0]); unpk2(l1, h1, Ac2[1]);
        q2[0] = make_float4(l0, h0, l1, h1);
        unpk2(l0, h0, Ac2[2]); unpk2(l1, h1, Ac2[3]);
        q2[1] = make_float4(l0, h0, l1, h1);
    }
}

// ---------------------------------------------------------------------------
// Inputs (metadata order): u, dt, A, B, bA, W1, b1, W2, b2
// Output: [outputs (3*SEQ) | membranes (3*SEQ)]
// ---------------------------------------------------------------------------
extern "C" void kernel_launch(void* const* d_in, const int* in_sizes, int n_in,
                              void* d_out, int out_size) {
    const float* u  = (const float*)d_in[0];
    const float* dt = (const float*)d_in[1];
    const float* A  = (const float*)d_in[2];
    const float* B  = (const float*)d_in[3];
    const float* bA = (const float*)d_in[4];
    const float* W1 = (const float*)d_in[5];
    const float* b1 = (const float*)d_in[6];
    const float* W2 = (const float*)d_in[7];
    const float* b2 = (const float*)d_in[8];
    float* out = (float*)d_out;

    fused_kernel<<<GRID, TPB>>>(u, dt, A, B, bA, W1, b1, W2, b2, out);
}

// round 16
// speedup vs baseline: 1.1523x; 1.1523x over previous
#include <cuda_runtime.h>

#define SEQ 262144
#define HID 256
#define L 8                    // timesteps per thread
#define P (SEQ / L)            // 32768 threads
#define TPB 256
#define NWARP (TPB / 32)
#define GRID (P / TPB)         // 128 CTAs, 1/SM, all resident -> barrier safe
#define NSWEEP 2

typedef unsigned long long ull;

// CTA-total affines, rows as float4 {Ji0,Ji1,Ji2,di}; double buffered
struct AffG { float4 r0, r1, r2; };
__device__ AffG g_tot[2][GRID];

// grid barrier: counters reset by last arriver; flags monotone across replays
__device__ unsigned g_cnt[NSWEEP];
__device__ unsigned g_flag[NSWEEP];

__device__ __forceinline__ float tanh_approx(float x) {
    float y; asm("tanh.approx.f32 %0, %1;" : "=f"(y) : "f"(x)); return y;
}

struct Aff { float J[9]; float d[3]; };

__device__ __forceinline__ Aff aff_identity() {
    Aff a;
    a.J[0] = 1.f; a.J[1] = 0.f; a.J[2] = 0.f;
    a.J[3] = 0.f; a.J[4] = 1.f; a.J[5] = 0.f;
    a.J[6] = 0.f; a.J[7] = 0.f; a.J[8] = 1.f;
    a.d[0] = a.d[1] = a.d[2] = 0.f;
    return a;
}

// result = hi ∘ lo (lo applied first)
__device__ __forceinline__ Aff aff_compose(const Aff& hi, const Aff& lo) {
    Aff r;
#pragma unroll
    for (int i = 0; i < 3; i++) {
#pragma unroll
        for (int j = 0; j < 3; j++) {
            r.J[i * 3 + j] = fmaf(hi.J[i * 3 + 0], lo.J[0 * 3 + j],
                             fmaf(hi.J[i * 3 + 1], lo.J[1 * 3 + j],
                                  hi.J[i * 3 + 2] * lo.J[2 * 3 + j]));
        }
        r.d[i] = fmaf(hi.J[i * 3 + 0], lo.d[0],
                 fmaf(hi.J[i * 3 + 1], lo.d[1],
                 fmaf(hi.J[i * 3 + 2], lo.d[2], hi.d[i])));
    }
    return r;
}

__device__ __forceinline__ Aff aff_shfl_up(const Aff& a, int off) {
    Aff r;
#pragma unroll
    for (int i = 0; i < 9; i++) r.J[i] = __shfl_up_sync(0xFFFFFFFFu, a.J[i], off);
#pragma unroll
    for (int i = 0; i < 3; i++) r.d[i] = __shfl_up_sync(0xFFFFFFFFu, a.d[i], off);
    return r;
}

#define FMA2(d, a, bb, c) \
    asm("fma.rn.f32x2 %0, %1, %2, %3;" : "=l"(d) : "l"(a), "l"(bb), "l"(c))

__device__ __forceinline__ ull pk2(float a, float b) {
    ull r; asm("mov.b64 %0, {%1, %2};" : "=l"(r) : "f"(a), "f"(b)); return r;
}
__device__ __forceinline__ void unpk2(float& lo, float& hi, ull d) {
    asm("mov.b64 {%0, %1}, %2;" : "=f"(lo), "=f"(hi) : "l"(d));
}

// ---------------------------------------------------------------------------
// ONE kernel: prep (w in registers) + 2 Newton-parareal sweeps (first-order
// Jacobian; fixed point J-independent) + final fine pass + store + fused MLP.
// Barrier uses scoped acquire/release atomics (no MEMBAR.GPU on the path).
// ---------------------------------------------------------------------------
__global__ void __launch_bounds__(TPB, 1)
fused_kernel(const float* __restrict__ u,
             const float* __restrict__ dtp,
             const float* __restrict__ Ain,
             const float* __restrict__ Bin,
             const float* __restrict__ bAin,
             const float* __restrict__ W1,
             const float* __restrict__ b1,
             const float* __restrict__ W2,
             const float* __restrict__ b2,
             float* __restrict__ out) {
    float* memb = out + 3 * SEQ;

    int tid  = threadIdx.x;
    int lane = tid & 31;
    int wid  = tid >> 5;
    int cta  = blockIdx.x;
    int b    = cta * TPB + tid;

    __shared__ Aff    warpTot[NWARP];
    __shared__ Aff    warpPre[NWARP];
    __shared__ float4 sVall[GRID];   // V vectors for every CTA (2KB)
    __shared__ ull    sA[HID * 4];   // per h: {w0w0, w1w1, w2w2, b1b1}
    __shared__ ull    sB[HID * 4];   // per h: {v0v0, v1v1, v2v2, 0}

    // ---- MLP weight staging (used only in the final phase) ----
    {
        int h = tid;  // TPB == HID
        sA[4 * h + 0] = pk2(W1[3 * h + 0], W1[3 * h + 0]);
        sA[4 * h + 1] = pk2(W1[3 * h + 1], W1[3 * h + 1]);
        sA[4 * h + 2] = pk2(W1[3 * h + 2], W1[3 * h + 2]);
        sA[4 * h + 3] = pk2(b1[h], b1[h]);
        sB[4 * h + 0] = pk2(W2[h], W2[h]);
        sB[4 * h + 1] = pk2(W2[HID + h], W2[HID + h]);
        sB[4 * h + 2] = pk2(W2[2 * HID + h], W2[2 * HID + h]);
        sB[4 * h + 3] = 0ull;
    }

    float dt = *dtp;
    float A00 = __ldg(Ain + 0), A01 = __ldg(Ain + 1), A02 = __ldg(Ain + 2);
    float A10 = __ldg(Ain + 3), A11 = __ldg(Ain + 4), A12 = __ldg(Ain + 5);
    float A20 = __ldg(Ain + 6), A21 = __ldg(Ain + 7), A22 = __ldg(Ain + 8);

    // ---- prep: w for own 8 timesteps, kept in registers ----
    float w0r[L], w1r[L], w2r[L];
    {
        float b00 = __ldg(Bin + 0), b01 = __ldg(Bin + 1), b02 = __ldg(Bin + 2);
        float b10 = __ldg(Bin + 3), b11 = __ldg(Bin + 4), b12 = __ldg(Bin + 5);
        float b20 = __ldg(Bin + 6), b21 = __ldg(Bin + 7), b22 = __ldg(Bin + 8);
        float a0 = __ldg(bAin + 0), a1 = __ldg(bAin + 1), a2 = __ldg(bAin + 2);
        const float* ub = u + b * L;
#pragma unroll
        for (int q = 0; q < 2; q++) {
            float4 ua = *(const float4*)(ub + 4 * q);
            float4 va = *(const float4*)(ub + SEQ + 4 * q);
            float4 za = *(const float4*)(ub + 2 * SEQ + 4 * q);
            float U0[4] = {ua.x, ua.y, ua.z, ua.w};
            float U1[4] = {va.x, va.y, va.z, va.w};
            float U2[4] = {za.x, za.y, za.z, za.w};
#pragma unroll
            for (int e = 0; e < 4; e++) {
                int j = 4 * q + e;
                w0r[j] = fmaf(b00, U0[e], fmaf(b01, U1[e], fmaf(b02, U2[e], a0)));
                w1r[j] = fmaf(b10, U0[e], fmaf(b11, U1[e], fmaf(b12, U2[e], a1)));
                w2r[j] = fmaf(b20, U0[e], fmaf(b21, U1[e], fmaf(b22, U2[e], a2)));
            }
        }
    }

    float s0 = 0.f, s1 = 0.f, s2 = 0.f;

    for (int sweep = 0; sweep < NSWEEP; sweep++) {
        int buf = sweep & 1;

        // ---- fine pass; accumulate ΣD for first-order Jacobian ----
        float x0 = s0, x1 = s1, x2 = s2;
        float SD0 = 0.f, SD1 = 0.f, SD2 = 0.f;
#pragma unroll
        for (int j = 0; j < L; j++) {
            float y0 = fmaf(A00, x0, fmaf(A01, x1, fmaf(A02, x2, w0r[j])));
            float y1 = fmaf(A10, x0, fmaf(A11, x1, fmaf(A12, x2, w1r[j])));
            float y2 = fmaf(A20, x0, fmaf(A21, x1, fmaf(A22, x2, w2r[j])));
            float t0 = tanh_approx(y0);
            float t1 = tanh_approx(y1);
            float t2 = tanh_approx(y2);
            x0 = fmaf(dt, t0, x0);
            x1 = fmaf(dt, t1, x1);
            x2 = fmaf(dt, t2, x2);
            SD0 += fmaf(-t0, t0, 1.0f);
            SD1 += fmaf(-t1, t1, 1.0f);
            SD2 += fmaf(-t2, t2, 1.0f);
        }

        // ---- block affine: J ≈ I + (dt·SD_i)·A_ij ; d = E - J s ----
        Aff m;
        {
            float d0 = dt * SD0, d1 = dt * SD1, d2 = dt * SD2;
            m.J[0] = fmaf(d0, A00, 1.f); m.J[1] = d0 * A01;          m.J[2] = d0 * A02;
            m.J[3] = d1 * A10;           m.J[4] = fmaf(d1, A11, 1.f); m.J[5] = d1 * A12;
            m.J[6] = d2 * A20;           m.J[7] = d2 * A21;          m.J[8] = fmaf(d2, A22, 1.f);
        }
        m.d[0] = x0 - fmaf(m.J[0], s0, fmaf(m.J[1], s1, m.J[2] * s2));
        m.d[1] = x1 - fmaf(m.J[3], s0, fmaf(m.J[4], s1, m.J[5] * s2));
        m.d[2] = x2 - fmaf(m.J[6], s0, fmaf(m.J[7], s1, m.J[8] * s2));

        // ---- warp inclusive Kogge-Stone + thread-exclusive ----
        Aff inc = m;
#pragma unroll
        for (int off = 1; off < 32; off <<= 1) {
            Aff o = aff_shfl_up(inc, off);
            if (lane >= off) inc = aff_compose(inc, o);
        }
        Aff exc = aff_shfl_up(inc, 1);
        if (lane == 0) exc = aff_identity();
        if (lane == 31) warpTot[wid] = inc;
        __syncthreads();

        // ---- thread 0: CTA combine, publish total, grid barrier ----
        // acquire/release atomics replace the MEMBAR.GPU-heavy protocol:
        //   arrival = atom.add.acq_rel (release: orders g_tot stores to L2)
        //   release = st.release flag; waiters spin on ld.acquire.
        // Cross-CTA data is then read via __ldcg (L2-direct).
        if (tid == 0) {
            Aff run = aff_identity();
#pragma unroll
            for (int w = 0; w < NWARP; w++) {
                warpPre[w] = run;
                run = aff_compose(warpTot[w], run);
            }
            AffG t;
            t.r0 = make_float4(run.J[0], run.J[1], run.J[2], run.d[0]);
            t.r1 = make_float4(run.J[3], run.J[4], run.J[5], run.d[1]);
            t.r2 = make_float4(run.J[6], run.J[7], run.J[8], run.d[2]);
            g_tot[buf][cta] = t;

            // flag read BEFORE arriving: race-free (flag can't advance until
            // this CTA arrives).
            unsigned old = g_flag[sweep];
            unsigned n;
            asm volatile("atom.global.add.acq_rel.gpu.u32 %0, [%1], 1;"
                         : "=r"(n) : "l"(&g_cnt[sweep]) : "memory");
            if (n == GRID - 1) {
                g_cnt[sweep] = 0;    // clean for next graph replay
                asm volatile("st.global.release.gpu.u32 [%0], %1;"
                             :: "l"(&g_flag[sweep]), "r"(old + 1u) : "memory");
            } else {
                unsigned f;
                do {
                    asm volatile("ld.global.acquire.gpu.u32 %0, [%1];"
                                 : "=r"(f) : "l"(&g_flag[sweep]) : "memory");
                } while (f == old);
            }
        }
        __syncthreads();

        // ---- warp 0: parallel scan over all 128 CTA totals -> V vectors ----
        if (wid == 0) {
            Aff t4[4];
#pragma unroll
            for (int r = 0; r < 4; r++) {
                int c = 4 * lane + r;
                float4 q0 = __ldcg(&g_tot[buf][c].r0);
                float4 q1 = __ldcg(&g_tot[buf][c].r1);
                float4 q2 = __ldcg(&g_tot[buf][c].r2);
                t4[r].J[0] = q0.x; t4[r].J[1] = q0.y; t4[r].J[2] = q0.z; t4[r].d[0] = q0.w;
                t4[r].J[3] = q1.x; t4[r].J[4] = q1.y; t4[r].J[5] = q1.z; t4[r].d[1] = q1.w;
                t4[r].J[6] = q2.x; t4[r].J[7] = q2.y; t4[r].J[8] = q2.z; t4[r].d[2] = q2.w;
            }
            Aff Pp1 = t4[0];
            Aff Pp2 = aff_compose(t4[1], Pp1);
            Aff Pp3 = aff_compose(t4[2], Pp2);
            Aff laneTot = aff_compose(t4[3], Pp3);
            Aff incL = laneTot;
#pragma unroll
            for (int off = 1; off < 32; off <<= 1) {
                Aff o = aff_shfl_up(incL, off);
                if (lane >= off) incL = aff_compose(incL, o);
            }
            Aff excL = aff_shfl_up(incL, 1);
            if (lane == 0) excL = aff_identity();
            float e0 = excL.d[0], e1 = excL.d[1], e2 = excL.d[2];
            sVall[4 * lane + 0] = make_float4(e0, e1, e2, 0.f);
#define APPLY_STORE(PP, idx)                                                    \
            sVall[4 * lane + idx] = make_float4(                                \
                fmaf((PP).J[0], e0, fmaf((PP).J[1], e1, fmaf((PP).J[2], e2, (PP).d[0]))), \
                fmaf((PP).J[3], e0, fmaf((PP).J[4], e1, fmaf((PP).J[5], e2, (PP).d[1]))), \
                fmaf((PP).J[6], e0, fmaf((PP).J[7], e1, fmaf((PP).J[8], e2, (PP).d[2]))), 0.f)
            APPLY_STORE(Pp1, 1);
            APPLY_STORE(Pp2, 2);
            APPLY_STORE(Pp3, 3);
#undef APPLY_STORE
        }
        __syncthreads();

        // ---- Newton update: s = exc( warpPre[wid]( V ) ) ----
        float4 V4 = sVall[cta];
        {
            const Aff& p = warpPre[wid];
            float t0 = fmaf(p.J[0], V4.x, fmaf(p.J[1], V4.y, fmaf(p.J[2], V4.z, p.d[0])));
            float t1 = fmaf(p.J[3], V4.x, fmaf(p.J[4], V4.y, fmaf(p.J[5], V4.z, p.d[1])));
            float t2 = fmaf(p.J[6], V4.x, fmaf(p.J[7], V4.y, fmaf(p.J[8], V4.z, p.d[2])));
            s0 = fmaf(exc.J[0], t0, fmaf(exc.J[1], t1, fmaf(exc.J[2], t2, exc.d[0])));
            s1 = fmaf(exc.J[3], t0, fmaf(exc.J[4], t1, fmaf(exc.J[5], t2, exc.d[1])));
            s2 = fmaf(exc.J[6], t0, fmaf(exc.J[7], t1, fmaf(exc.J[8], t2, exc.d[2])));
        }
        // protect warpTot/warpPre/sVall reuse — needed only between sweeps
        if (sweep + 1 < NSWEEP) __syncthreads();
    }

    // ---- final trajectory: compute in registers, store membranes ----
    float xs0[L], xs1[L], xs2[L];
    {
        float x0 = s0, x1 = s1, x2 = s2;
#pragma unroll
        for (int j = 0; j < L; j++) {
            float y0 = fmaf(A00, x0, fmaf(A01, x1, fmaf(A02, x2, w0r[j])));
            float y1 = fmaf(A10, x0, fmaf(A11, x1, fmaf(A12, x2, w1r[j])));
            float y2 = fmaf(A20, x0, fmaf(A21, x1, fmaf(A22, x2, w2r[j])));
            x0 = fmaf(dt, tanh_approx(y0), x0);
            x1 = fmaf(dt, tanh_approx(y1), x1);
            x2 = fmaf(dt, tanh_approx(y2), x2);
            xs0[j] = x0; xs1[j] = x1; xs2[j] = x2;
        }
        float4* o0 = (float4*)(memb + b * L);
        float4* o1 = (float4*)(memb + SEQ + b * L);
        float4* o2 = (float4*)(memb + 2 * SEQ + b * L);
        o0[0] = make_float4(xs0[0], xs0[1], xs0[2], xs0[3]);
        o0[1] = make_float4(xs0[4], xs0[5], xs0[6], xs0[7]);
        o1[0] = make_float4(xs1[0], xs1[1], xs1[2], xs1[3]);
        o1[1] = make_float4(xs1[4], xs1[5], xs1[6], xs1[7]);
        o2[0] = make_float4(xs2[0], xs2[1], xs2[2], xs2[3]);
        o2[1] = make_float4(xs2[4], xs2[5], xs2[6], xs2[7]);
    }

    // ---- fused MLP on register-resident trajectory (4 f32x2 pairs) ----
    {
        ull X0[4], X1[4], X2[4], Ac0[4], Ac1[4], Ac2[4];
        ull bz0 = pk2(b2[0], b2[0]), bz1 = pk2(b2[1], b2[1]), bz2 = pk2(b2[2], b2[2]);
#pragma unroll
        for (int k = 0; k < 4; k++) {
            X0[k] = pk2(xs0[2 * k], xs0[2 * k + 1]);
            X1[k] = pk2(xs1[2 * k], xs1[2 * k + 1]);
            X2[k] = pk2(xs2[2 * k], xs2[2 * k + 1]);
            Ac0[k] = bz0; Ac1[k] = bz1; Ac2[k] = bz2;
        }

#pragma unroll 8
        for (int h = 0; h < HID; h++) {
            ulonglong2 a0 = ((const ulonglong2*)sA)[2 * h];       // {w0w0, w1w1}
            ulonglong2 a1 = ((const ulonglong2*)sA)[2 * h + 1];   // {w2w2, bbbb}
            ulonglong2 v0 = ((const ulonglong2*)sB)[2 * h];       // {v0v0, v1v1}
            ulonglong2 v1 = ((const ulonglong2*)sB)[2 * h + 1];   // {v2v2, --}
#pragma unroll
            for (int p = 0; p < 4; p++) {
                ull hv;
                FMA2(hv, a0.x, X0[p], a1.y);
                FMA2(hv, a0.y, X1[p], hv);
                FMA2(hv, a1.x, X2[p], hv);
                float lo, hi;
                unpk2(lo, hi, hv);
                lo = fmaxf(lo, 0.0f);
                hi = fmaxf(hi, 0.0f);
                hv = pk2(lo, hi);
                FMA2(Ac0[p], v0.x, hv, Ac0[p]);
                FMA2(Ac1[p], v0.y, hv, Ac1[p]);
                FMA2(Ac2[p], v1.x, hv, Ac2[p]);
            }
        }

        // vectorized output stores: 2 float4 per plane
        float4* q0 = (float4*)(out + b * L);
        float4* q1 = (float4*)(out + SEQ + b * L);
        float4* q2 = (float4*)(out + 2 * SEQ + b * L);
        float l0, h0, l1, h1;
        unpk2(l0, h0, Ac0[0]); unpk2(l1, h1, Ac0[1]);
        q0[0] = make_float4(l0, h0, l1, h1);
        unpk2(l0, h0, Ac0[2]); unpk2(l1, h1, Ac0[3]);
        q0[1] = make_float4(l0, h0, l1, h1);
        unpk2(l0, h0, Ac1[0]); unpk2(l1, h1, Ac1[1]);
        q1[0] = make_float4(l0, h0, l1, h1);
        unpk2(l0, h0, Ac1[2]); unpk2(l1, h1, Ac1[3]);
        q1[1] = make_float4(l0, h0, l1, h1);
        unpk2(l0, h0, Ac2[0]); unpk2(l1, h1, Ac2[1]);
        q2[0] = make_float4(l0, h0, l1, h1);
        unpk2(l0, h0, Ac2[2]); unpk2(l1, h1, Ac2[3]);
        q2[1] = make_float4(l0, h0, l1, h1);
    }
}

// ---------------------------------------------------------------------------
// Inputs (metadata order): u, dt, A, B, bA, W1, b1, W2, b2
// Output: [outputs (3*SEQ) | membranes (3*SEQ)]
// ---------------------------------------------------------------------------
extern "C" void kernel_launch(void* const* d_in, const int* in_sizes, int n_in,
                              void* d_out, int out_size) {
    const float* u  = (const float*)d_in[0];
    const float* dt = (const float*)d_in[1];
    const float* A  = (const float*)d_in[2];
    const float* B  = (const float*)d_in[3];
    const float* bA = (const float*)d_in[4];
    const float* W1 = (const float*)d_in[5];
    const float* b1 = (const float*)d_in[6];
    const float* W2 = (const float*)d_in[7];
    const float* b2 = (const float*)d_in[8];
    float* out = (float*)d_out;

    fused_kernel<<<GRID, TPB>>>(u, dt, A, B, bA, W1, b1, W2, b2, out);
}